// round 11
// baseline (speedup 1.0000x reference)
#include <cuda_runtime.h>

#define NP      262144
#define NT      32                  // tiles
#define TILE    8192                // particles per tile (NP/NT)
#define TSHIFT  13                  // log2(TILE)
#define TMASK   8191
#define NBINS   528                 // NT*(NT+1)/2 unordered tile pairs
#define CAP     20480               // max pairs per bin (mean 16384, +32 sigma)
#define CHUNK   4096                // pairs per bin-kernel block

__device__ float g_xs[NP];
__device__ float g_ys[NP];
__device__ float g_zs[NP];
__device__ unsigned int g_cursor[NBINS];
__device__ unsigned int g_pairs[NBINS * (unsigned)CAP];   // ~43 MB
__device__ double g_sum;
__device__ unsigned int g_count;

// ---------------------------------------------------------------------------
// Pass A: repack x [N,3] -> SoA xs/ys/zs, zero cursors + accumulators.
// Each thread handles 4 particles (3x float4 loads, 3x float4 stores).
__global__ void repack_kernel(const float4* __restrict__ x4, int n_quads) {
    int t = blockIdx.x * blockDim.x + threadIdx.x;
    if (t == 0) { g_sum = 0.0; g_count = 0u; }
    if (t < NBINS) g_cursor[t] = 0u;
    if (t < n_quads) {
        float4 a = x4[3 * t + 0];   // p0.x p0.y p0.z p1.x
        float4 b = x4[3 * t + 1];   // p1.y p1.z p2.x p2.y
        float4 c = x4[3 * t + 2];   // p2.z p3.x p3.y p3.z
        ((float4*)g_xs)[t] = make_float4(a.x, a.w, b.z, c.y);
        ((float4*)g_ys)[t] = make_float4(a.y, b.x, b.w, c.z);
        ((float4*)g_zs)[t] = make_float4(a.z, b.y, c.x, c.w);
    }
}

// ---------------------------------------------------------------------------
// Pass B: bin pairs by unordered tile pair. One pass: stage chunk in smem,
// smem histogram, one global reservation atomic per bin, scatter packed
// local-index pairs (la | lb<<13).
__global__ void __launch_bounds__(256) bin_kernel(
        const int4* __restrict__ idx_i4,
        const int4* __restrict__ idx_j4) {
    __shared__ int si[CHUNK];
    __shared__ int sj[CHUNK];
    __shared__ unsigned int hist[NBINS];
    __shared__ unsigned int base[NBINS];

    int tid = threadIdx.x;
    int vbase = blockIdx.x * (CHUNK / 4);   // int4 index base for this block

    // stage CHUNK pairs (1024 int4 per stream, 4 per thread)
#pragma unroll
    for (int r = 0; r < 4; r++) {
        int v = vbase + r * 256 + tid;
        int4 iv = idx_i4[v];
        int4 jv = idx_j4[v];
        int p = (r * 256 + tid) * 4;
        si[p + 0] = iv.x; si[p + 1] = iv.y; si[p + 2] = iv.z; si[p + 3] = iv.w;
        sj[p + 0] = jv.x; sj[p + 1] = jv.y; sj[p + 2] = jv.z; sj[p + 3] = jv.w;
    }
    for (int b = tid; b < NBINS; b += 256) hist[b] = 0u;
    __syncthreads();

    // histogram (16 pairs per thread)
#pragma unroll 4
    for (int k = 0; k < 16; k++) {
        int p = tid * 16 + k;
        int ti = si[p] >> TSHIFT;
        int tj = sj[p] >> TSHIFT;
        int a = min(ti, tj), b = max(ti, tj);
        int bin = a * NT - (a * (a - 1)) / 2 + (b - a);
        atomicAdd(&hist[bin], 1u);
    }
    __syncthreads();

    // reserve global ranges; reuse hist as local cursor
    for (int b = tid; b < NBINS; b += 256) {
        unsigned int c = hist[b];
        base[b] = c ? atomicAdd(&g_cursor[b], c) : 0u;
        hist[b] = 0u;
    }
    __syncthreads();

    // scatter
#pragma unroll 4
    for (int k = 0; k < 16; k++) {
        int p = tid * 16 + k;
        int i = si[p], j = sj[p];
        int ti = i >> TSHIFT, tj = j >> TSHIFT;
        int a = min(ti, tj), b = max(ti, tj);
        int bin = a * NT - (a * (a - 1)) / 2 + (b - a);
        unsigned int la = (unsigned)((ti <= tj) ? i : j) & TMASK;
        unsigned int lb = (unsigned)((ti <= tj) ? j : i) & TMASK;
        unsigned int off = base[bin] + atomicAdd(&hist[bin], 1u);
        if (off < CAP)
            g_pairs[(unsigned)bin * CAP + off] = la | (lb << TSHIFT);
    }
}

// ---------------------------------------------------------------------------
// Pass C: one block per bin. Load tile a and tile b into smem (SoA fp32),
// stream packed pairs as uint4 (4 pairs/thread-load), gather via LDS.
__global__ void __launch_bounds__(512) lj_main(
        const float* __restrict__ eps_p,
        const float* __restrict__ sigma_p,
        const float* __restrict__ box_p,
        float* __restrict__ out) {
    extern __shared__ float smem[];
    float* xsA = smem;
    float* ysA = smem + TILE;
    float* zsA = smem + 2 * TILE;
    float* xsB = smem + 3 * TILE;
    float* ysB = smem + 4 * TILE;
    float* zsB = smem + 5 * TILE;

    // decode bin -> (a, b)
    int id = blockIdx.x;
    int a = 0;
    while (id >= NT - a) { id -= NT - a; a++; }
    int b = a + id;

    int tid = threadIdx.x;
    for (int k = tid; k < TILE; k += 512) {
        xsA[k] = g_xs[a * TILE + k];
        ysA[k] = g_ys[a * TILE + k];
        zsA[k] = g_zs[a * TILE + k];
        xsB[k] = g_xs[b * TILE + k];
        ysB[k] = g_ys[b * TILE + k];
        zsB[k] = g_zs[b * TILE + k];
    }
    __syncthreads();

    const float L = box_p[0];
    const float invL = 1.0f / L;
    const float sigma = sigma_p[0];
    const float sigma2 = sigma * sigma;

    int bin = blockIdx.x;
    unsigned int cnt = g_cursor[bin];
    if (cnt > CAP) cnt = CAP;
    const uint4* pp4 = (const uint4*)&g_pairs[(unsigned)bin * CAP];
    unsigned int n4v = cnt >> 2;

    float acc = 0.0f;

    for (unsigned int v = tid; v < n4v; v += 512) {
        uint4 u4 = pp4[v];
        unsigned int us[4] = {u4.x, u4.y, u4.z, u4.w};
#pragma unroll
        for (int k = 0; k < 4; k++) {
            unsigned int u = us[k];
            int la = u & TMASK;
            int lb = (u >> TSHIFT) & TMASK;
            float dx = xsA[la] - xsB[lb];
            float dy = ysA[la] - ysB[lb];
            float dz = zsA[la] - zsB[lb];
            dx -= L * rintf(dx * invL);
            dy -= L * rintf(dy * invL);
            dz -= L * rintf(dz * invL);
            float r2 = fmaf(dx, dx, fmaf(dy, dy, dz * dz));
            float s2 = sigma2 / r2;
            float s6 = s2 * s2 * s2;
            acc += fmaf(s6, s6, -s6);
        }
    }
    // tail (cnt % 4 pairs)
    for (unsigned int v = (n4v << 2) + tid; v < cnt; v += 512) {
        unsigned int u = g_pairs[(unsigned)bin * CAP + v];
        int la = u & TMASK;
        int lb = (u >> TSHIFT) & TMASK;
        float dx = xsA[la] - xsB[lb];
        float dy = ysA[la] - ysB[lb];
        float dz = zsA[la] - zsB[lb];
        dx -= L * rintf(dx * invL);
        dy -= L * rintf(dy * invL);
        dz -= L * rintf(dz * invL);
        float r2 = fmaf(dx, dx, fmaf(dy, dy, dz * dz));
        float s2 = sigma2 / r2;
        float s6 = s2 * s2 * s2;
        acc += fmaf(s6, s6, -s6);
    }

    acc *= 4.0f * eps_p[0];

    // warp reduce (float), block reduce in double, one atomic per block
    for (int off = 16; off > 0; off >>= 1)
        acc += __shfl_down_sync(0xFFFFFFFFu, acc, off);

    __shared__ double warp_sums[16];
    int lane = tid & 31;
    int wid = tid >> 5;
    if (lane == 0) warp_sums[wid] = (double)acc;
    __syncthreads();

    if (wid == 0) {
        double s = (lane < 16) ? warp_sums[lane] : 0.0;
        for (int off = 8; off > 0; off >>= 1)
            s += __shfl_down_sync(0xFFFFFFFFu, s, off);
        if (lane == 0) {
            atomicAdd(&g_sum, s);
            __threadfence();
            unsigned int ticket = atomicAdd(&g_count, 1u);
            if (ticket == gridDim.x - 1) {
                out[0] = (float)g_sum;
            }
        }
    }
}

// ---------------------------------------------------------------------------
extern "C" void kernel_launch(void* const* d_in, const int* in_sizes, int n_in,
                              void* d_out, int out_size) {
    const float* x       = (const float*)d_in[0];   // [N,3]
    const float* eps_p   = (const float*)d_in[1];   // scalar
    const float* sigma_p = (const float*)d_in[2];   // scalar
    const float* box_p   = (const float*)d_in[3];   // [3]
    const int*   idx_i   = (const int*)d_in[4];     // [n_pairs]
    const int*   idx_j   = (const int*)d_in[5];     // [n_pairs]

    int n_particles = in_sizes[0] / 3;
    int n_pairs     = in_sizes[4];
    int n_quads     = n_particles / 4;     // 65536
    int bin_blocks  = n_pairs / CHUNK;     // 2048 (8388608 / 4096)

    const int MAIN_SMEM = 6 * TILE * sizeof(float);   // 192 KB
    cudaFuncSetAttribute(lj_main, cudaFuncAttributeMaxDynamicSharedMemorySize,
                         MAIN_SMEM);

    // Pass A: repack + zero
    {
        int threads = 256;
        int blocks = (n_quads + threads - 1) / threads;
        repack_kernel<<<blocks, threads>>>((const float4*)x, n_quads);
    }

    // Pass B: bin pairs
    bin_kernel<<<bin_blocks, 256>>>((const int4*)idx_i, (const int4*)idx_j);

    // Pass C: per-bin LJ with smem gathers (fused finalize)
    lj_main<<<NBINS, 512, MAIN_SMEM>>>(eps_p, sigma_p, box_p, (float*)d_out);
}

// round 12
// speedup vs baseline: 2.0640x; 2.0640x over previous
#include <cuda_runtime.h>

#define N_PARTICLES_MAX 262144

__device__ float4 g_x4[N_PARTICLES_MAX];
__device__ double g_sum;
__device__ unsigned int g_count;

// Repack x [N,3] -> float4 (16B-aligned), zero accumulator + ticket counter.
// One particle per thread: 3 coalesced scalar loads + 1 float4 store.
__global__ void repack_kernel(const float* __restrict__ x, int n) {
    int p = blockIdx.x * blockDim.x + threadIdx.x;
    if (p == 0) { g_sum = 0.0; g_count = 0u; }
    if (p < n) {
        float a = x[3 * p + 0];
        float b = x[3 * p + 1];
        float c = x[3 * p + 2];
        g_x4[p] = make_float4(a, b, c, 0.0f);
    }
}

// Each thread processes 4 pairs (one int4 from each index stream).
// Exact round-1 record inner loop. Last block writes the final result.
__global__ void __launch_bounds__(256) lj_kernel(
        const int4* __restrict__ idx_i4,
        const int4* __restrict__ idx_j4,
        const float* __restrict__ eps_p,
        const float* __restrict__ sigma_p,
        const float* __restrict__ box_p,
        int n4,
        float* __restrict__ out) {
    const float L = box_p[0];
    const float invL = __fdividef(1.0f, L);
    const float sigma = sigma_p[0];
    const float sigma2 = sigma * sigma;

    float acc = 0.0f;

    int t = blockIdx.x * blockDim.x + threadIdx.x;
    int stride = gridDim.x * blockDim.x;
    for (int v = t; v < n4; v += stride) {
        int4 iv = __ldcs(&idx_i4[v]);
        int4 jv = __ldcs(&idx_j4[v]);
        int is[4] = {iv.x, iv.y, iv.z, iv.w};
        int js[4] = {jv.x, jv.y, jv.z, jv.w};
#pragma unroll
        for (int k = 0; k < 4; k++) {
            float4 pi = __ldg(&g_x4[is[k]]);
            float4 pj = __ldg(&g_x4[js[k]]);
            float dx = pi.x - pj.x;
            float dy = pi.y - pj.y;
            float dz = pi.z - pj.z;
            dx -= L * rintf(dx * invL);
            dy -= L * rintf(dy * invL);
            dz -= L * rintf(dz * invL);
            float r2 = fmaf(dx, dx, fmaf(dy, dy, dz * dz));
            float s2 = sigma2 * __fdividef(1.0f, r2);
            float s6 = s2 * s2 * s2;
            acc += fmaf(s6, s6, -s6);   // s12 - s6
        }
    }

    acc *= 4.0f * eps_p[0];

    // warp reduce (float), then block reduce in double, one atomic per block
    for (int off = 16; off > 0; off >>= 1)
        acc += __shfl_down_sync(0xFFFFFFFFu, acc, off);

    __shared__ double warp_sums[8];
    int lane = threadIdx.x & 31;
    int wid  = threadIdx.x >> 5;
    if (lane == 0) warp_sums[wid] = (double)acc;
    __syncthreads();

    if (wid == 0) {
        double s = (lane < 8) ? warp_sums[lane] : 0.0;
        for (int off = 4; off > 0; off >>= 1)
            s += __shfl_down_sync(0xFFFFFFFFu, s, off);
        if (lane == 0) {
            atomicAdd(&g_sum, s);
            __threadfence();
            unsigned int ticket = atomicAdd(&g_count, 1u);
            if (ticket == gridDim.x - 1) {
                out[0] = (float)g_sum;
            }
        }
    }
}

extern "C" void kernel_launch(void* const* d_in, const int* in_sizes, int n_in,
                              void* d_out, int out_size) {
    const float* x       = (const float*)d_in[0];   // [N,3]
    const float* eps_p   = (const float*)d_in[1];   // scalar
    const float* sigma_p = (const float*)d_in[2];   // scalar
    const float* box_p   = (const float*)d_in[3];   // [3]
    const int*   idx_i   = (const int*)d_in[4];     // [n_pairs]
    const int*   idx_j   = (const int*)d_in[5];     // [n_pairs]

    int n_particles = in_sizes[0] / 3;
    int n_pairs     = in_sizes[4];
    int n4          = n_pairs / 4;       // 2M quads of 4 pairs

    // 1) repack + zero accumulators (one particle per thread)
    {
        int threads = 128;
        int blocks = (n_particles + threads - 1) / threads;  // 2048
        repack_kernel<<<blocks, threads>>>(x, n_particles);
    }

    // 2) main pair kernel (fused finalize)
    {
        int threads = 256;
        int blocks = (n4 + threads - 1) / threads;           // 8192
        lj_kernel<<<blocks, threads>>>((const int4*)idx_i, (const int4*)idx_j,
                                       eps_p, sigma_p, box_p, n4,
                                       (float*)d_out);
    }
}

// round 14
// speedup vs baseline: 2.2709x; 1.1002x over previous
#include <cuda_runtime.h>

#define N_PARTICLES_MAX 262144

__device__ float4 g_x4[N_PARTICLES_MAX];
__device__ double g_sum;
__device__ unsigned int g_count;

// Repack x [N,3] -> float4 (16B-aligned), zero accumulator + ticket counter.
// One particle per thread: 3 coalesced scalar loads + 1 float4 store.
__global__ void repack_kernel(const float* __restrict__ x, int n) {
    int p = blockIdx.x * blockDim.x + threadIdx.x;
    if (p == 0) { g_sum = 0.0; g_count = 0u; }
    if (p < n) {
        float a = x[3 * p + 0];
        float b = x[3 * p + 1];
        float c = x[3 * p + 2];
        g_x4[p] = make_float4(a, b, c, 0.0f);
    }
}

// Persistent main kernel: one wave (148 SMs x 8 CTAs), grid-stride over all
// quads. Round-7 inner loop (best measured). Last block writes the result.
__global__ void lj_kernel(const int4* __restrict__ idx_i4,
                          const int4* __restrict__ idx_j4,
                          const float* __restrict__ eps_p,
                          const float* __restrict__ sigma_p,
                          const float* __restrict__ box_p,
                          int n4,
                          float* __restrict__ out) {
    const float L = box_p[0];
    const float invL = 1.0f / L;
    const float sigma = sigma_p[0];
    const float sigma2 = sigma * sigma;

    float acc = 0.0f;

    int t = blockIdx.x * blockDim.x + threadIdx.x;
    int stride = gridDim.x * blockDim.x;
    for (int v = t; v < n4; v += stride) {
        int4 iv = idx_i4[v];
        int4 jv = idx_j4[v];
        int is[4] = {iv.x, iv.y, iv.z, iv.w};
        int js[4] = {jv.x, jv.y, jv.z, jv.w};
#pragma unroll
        for (int k = 0; k < 4; k++) {
            float4 pi = __ldg(&g_x4[is[k]]);
            float4 pj = __ldg(&g_x4[js[k]]);
            float dx = pi.x - pj.x;
            float dy = pi.y - pj.y;
            float dz = pi.z - pj.z;
            dx -= L * rintf(dx * invL);
            dy -= L * rintf(dy * invL);
            dz -= L * rintf(dz * invL);
            float r2 = fmaf(dx, dx, fmaf(dy, dy, dz * dz));
            float s2 = sigma2 / r2;
            float s6 = s2 * s2 * s2;
            acc += fmaf(s6, s6, -s6);   // s12 - s6
        }
    }

    acc *= 4.0f * eps_p[0];

    // warp reduce (float), then block reduce in double, one atomic per block
    for (int off = 16; off > 0; off >>= 1)
        acc += __shfl_down_sync(0xFFFFFFFFu, acc, off);

    __shared__ double warp_sums[8];
    int lane = threadIdx.x & 31;
    int wid  = threadIdx.x >> 5;
    if (lane == 0) warp_sums[wid] = (double)acc;
    __syncthreads();

    if (wid == 0) {
        double s = (lane < 8) ? warp_sums[lane] : 0.0;
        for (int off = 4; off > 0; off >>= 1)
            s += __shfl_down_sync(0xFFFFFFFFu, s, off);
        if (lane == 0) {
            atomicAdd(&g_sum, s);
            __threadfence();
            unsigned int ticket = atomicAdd(&g_count, 1u);
            if (ticket == gridDim.x - 1) {
                out[0] = (float)g_sum;
            }
        }
    }
}

extern "C" void kernel_launch(void* const* d_in, const int* in_sizes, int n_in,
                              void* d_out, int out_size) {
    const float* x       = (const float*)d_in[0];   // [N,3]
    const float* eps_p   = (const float*)d_in[1];   // scalar
    const float* sigma_p = (const float*)d_in[2];   // scalar
    const float* box_p   = (const float*)d_in[3];   // [3]
    const int*   idx_i   = (const int*)d_in[4];     // [n_pairs]
    const int*   idx_j   = (const int*)d_in[5];     // [n_pairs]

    int n_particles = in_sizes[0] / 3;
    int n_pairs     = in_sizes[4];
    int n4          = n_pairs / 4;       // 2M quads of 4 pairs

    // 1) repack + zero accumulators (one particle per thread)
    {
        int threads = 128;
        int blocks = (n_particles + threads - 1) / threads;  // 2048
        repack_kernel<<<blocks, threads>>>(x, n_particles);
    }

    // 2) main pair kernel: persistent single wave (148 SMs x 8 CTAs of 256)
    {
        int threads = 256;
        int blocks  = 148 * 8;   // 1184 — one wave at 32 regs / 256 threads
        int max_blocks = (n4 + threads - 1) / threads;
        if (blocks > max_blocks) blocks = max_blocks;
        lj_kernel<<<blocks, threads>>>((const int4*)idx_i, (const int4*)idx_j,
                                       eps_p, sigma_p, box_p, n4,
                                       (float*)d_out);
    }
}